// round 10
// baseline (speedup 1.0000x reference)
#include <cuda_runtime.h>
#include <math_constants.h>
#include <math.h>
#include <cstdint>

#define TOKENS 16384
#define HIDDEN 7168
#define NEXP   256
#define TOPK   8
#define BK     16
#define NCH    (HIDDEN / BK)   // 448
#define TAU    1e-4f

// SMEM per stage: Adup [16][128 pairs] 16KB | B [16][256] f32 16KB = 32KB
#define ST_BYTES 32768
#define OFF_A    0
#define OFF_B    16384
// reused as 128x256 f32 logits buffer (128KB) after the main loop
#define SMEM_TOTAL 131072

__device__ float g_Bt[(size_t)NEXP * HIDDEN];    // chunk-blocked [ch][k][n]
__device__ int   g_nflag;
__device__ int   g_flagged[TOKENS];

#define CPA16(dst, src) \
    asm volatile("cp.async.cg.shared.global [%0], [%1], 16;" \
                 :: "r"(dst), "l"(src) : "memory")

#define LDSV2U64(r0, r1, addr) \
    asm volatile("ld.shared.v2.u64 {%0,%1}, [%2];" \
                 : "=l"(r0), "=l"(r1) : "r"(addr))

// ---------------------------------------------------------------------------
// Kernel 0: transpose W [n][k] -> g_Bt [chunk][k][n] (validated R8/R9).
// ---------------------------------------------------------------------------
__global__ __launch_bounds__(256)
void convert_b_kernel(const float* __restrict__ W) {
    if (blockIdx.x == 0 && threadIdx.x == 0) g_nflag = 0;   // per-launch reset

    const int ch = blockIdx.x;
    const int n  = threadIdx.x;
    const float* src = W + (size_t)n * HIDDEN + ch * BK;
    float* dst = g_Bt + (size_t)ch * (BK * NEXP);
    #pragma unroll
    for (int j = 0; j < 4; j++) {
        float4 v = *(const float4*)(src + 4 * j);
        dst[(4 * j + 0) * NEXP + n] = v.x;
        dst[(4 * j + 1) * NEXP + n] = v.y;
        dst[(4 * j + 2) * NEXP + n] = v.z;
        dst[(4 * j + 3) * NEXP + n] = v.w;
    }
}

// ---------------------------------------------------------------------------
// route_one: reference-exact routing for one token (validated R4-R9).
// ---------------------------------------------------------------------------
__device__ __forceinline__ void route_one(const float* __restrict__ row,
                                          const float* __restrict__ bias,
                                          float* __restrict__ out,
                                          int write_idx, int token, int lane,
                                          int do_flag)
{
    const unsigned FULL = 0xffffffffu;

    float4 l0 = *(const float4*)(row + lane * 8);
    float4 l1 = *(const float4*)(row + lane * 8 + 4);
    float4 b0 = *(const float4*)(bias + lane * 8);
    float4 b1 = *(const float4*)(bias + lane * 8 + 4);

    float lv[8] = {l0.x, l0.y, l0.z, l0.w, l1.x, l1.y, l1.z, l1.w};
    float bb[8] = {b0.x, b0.y, b0.z, b0.w, b1.x, b1.y, b1.z, b1.w};
    float sc[8], s4[8];
    #pragma unroll
    for (int i = 0; i < 8; i++) {
        float s = 1.0f / (1.0f + expf(-lv[i]));
        sc[i] = s;
        s4[i] = s + bb[i];
    }

    float m1 = -CUDART_INF_F, m2 = -CUDART_INF_F, m3 = -CUDART_INF_F;
    #pragma unroll
    for (int i = 0; i < 8; i++) {
        float v = s4[i];
        if (v > m1)      { m3 = m2; m2 = m1; m1 = v; }
        else if (v > m2) { m3 = m2; m2 = v; }
        else if (v > m3) { m3 = v; }
    }
    #pragma unroll
    for (int d = 1; d <= 2; d <<= 1) {
        float o1 = __shfl_xor_sync(FULL, m1, d);
        float o2 = __shfl_xor_sync(FULL, m2, d);
        float o3 = __shfl_xor_sync(FULL, m3, d);
        float mn1 = fminf(m1, o1);
        float mx2 = fmaxf(m2, o2);
        float n1 = fmaxf(m1, o1);
        float n2 = fmaxf(mn1, mx2);
        float n3 = fmaxf(fminf(mn1, mx2), fmaxf(m3, o3));
        m1 = n1; m2 = n2; m3 = n3;
    }
    const float gs  = m1 + m2;
    const float m23 = m2 - m3;
    const int   g   = lane >> 2;

    int rank = 0;
    #pragma unroll
    for (int j = 0; j < 8; j++) {
        float gj = __shfl_sync(FULL, gs, j * 4);
        rank += (gj > gs) || (gj == gs && j < g);
    }
    const int selg = (rank < 4);
    if (!selg) {
        #pragma unroll
        for (int i = 0; i < 8; i++) s4[i] = 0.0f;   // reference: score * mask
    }

    float flagmin = CUDART_INF_F;
    if (do_flag) {
        float vsel = selg ? gs : CUDART_INF_F;
        float vuns = selg ? -CUDART_INF_F : gs;
        float mm   = m23;
        #pragma unroll
        for (int d = 16; d; d >>= 1) {
            vsel = fminf(vsel, __shfl_xor_sync(FULL, vsel, d));
            vuns = fmaxf(vuns, __shfl_xor_sync(FULL, vuns, d));
            mm   = fminf(mm,   __shfl_xor_sync(FULL, mm,   d));
        }
        flagmin = fminf(vsel - vuns, mm);
    }

    float wsum = 0.0f, my_w = 0.0f, prevv = 0.0f;
    int   my_ix = 0;
    #pragma unroll
    for (int t = 0; t < 8; t++) {
        float bv = s4[0]; int bp = 0;
        #pragma unroll
        for (int i = 1; i < 8; i++)
            if (s4[i] > bv) { bv = s4[i]; bp = i; }
        float v  = bv;
        int   ix = lane * 8 + bp;
        #pragma unroll
        for (int d = 16; d; d >>= 1) {
            float ov = __shfl_xor_sync(FULL, v, d);
            int   oi = __shfl_xor_sync(FULL, ix, d);
            if (ov > v || (ov == v && oi < ix)) { v = ov; ix = oi; }
        }
        if (t > 0) flagmin = fminf(flagmin, prevv - v);
        prevv = v;
        const int opos  = ix & 7;
        const int olane = ix >> 3;
        #pragma unroll
        for (int i = 0; i < 8; i++)
            if (lane == olane && i == opos) s4[i] = -CUDART_INF_F;
        float cand = sc[0];
        #pragma unroll
        for (int i = 1; i < 8; i++)
            if (i == opos) cand = sc[i];
        float w = __shfl_sync(FULL, cand, olane);
        wsum += w;
        if (lane == t) { my_w = w; my_ix = ix; }
    }

    if (do_flag) {
        float bv = s4[0];
        #pragma unroll
        for (int i = 1; i < 8; i++) bv = fmaxf(bv, s4[i]);
        #pragma unroll
        for (int d = 16; d; d >>= 1)
            bv = fmaxf(bv, __shfl_xor_sync(FULL, bv, d));
        flagmin = fminf(flagmin, prevv - bv);
        if (lane == 0 && flagmin < TAU) {
            int p = atomicAdd(&g_nflag, 1);
            g_flagged[p] = token;
        }
    }

    const float scale = 2.5f / (wsum + 1e-20f);
    if (lane < TOPK) {
        out[(size_t)token * TOPK + lane] = my_w * scale;
        if (write_idx)
            out[(size_t)TOKENS * TOPK + (size_t)token * TOPK + lane] = (float)my_ix;
    }
}

// ---------------------------------------------------------------------------
// Kernel 1: fused SGEMM via fma.rn.f32x2 + routing.
// One 512-thread CTA per SM (grid 128, single wave), CTA = 128 x 256.
// Per-thread 8x8 f32 tile held as 32 u64 accumulators (8 rows x 4 col-pairs).
// A stored pair-duplicated in SMEM ({a,a}); warp-uniform A rows -> broadcast.
// ---------------------------------------------------------------------------
__global__ __launch_bounds__(512, 1)
void gemm_fx2(const float* __restrict__ A, const float* __restrict__ bias,
              float* __restrict__ out, int write_idx)
{
    extern __shared__ char smem[];
    uint32_t sb;
    asm("{ .reg .u64 t; cvta.to.shared.u64 t, %1; cvt.u32.u64 %0, t; }"
        : "=r"(sb) : "l"((void*)smem));

    const int tid = threadIdx.x;
    const int tx  = tid & 31;           // N: cols 8*tx .. 8*tx+7
    const int ty  = tid >> 5;           // M: rows ty*4..+3 and ty*4+64..+3
    const int bm  = blockIdx.x * 128;

    // A loader: 4 threads/row, 4 consecutive k each
    const int arow  = tid >> 2;
    const int apart = tid & 3;
    const float* Agp = A + (size_t)(bm + arow) * HIDDEN + apart * 4;

    unsigned long long c2[8][4];
    #pragma unroll
    for (int i = 0; i < 8; i++)
        #pragma unroll
        for (int j = 0; j < 4; j++) c2[i][j] = 0ULL;

#define LOAD_B_ASYNC(nc, st) do {                                              \
        const float* __s = g_Bt + (size_t)(nc) * (BK * NEXP) + tid * 8;        \
        uint32_t __d = sb + (st) * ST_BYTES + OFF_B + tid * 32;                \
        CPA16(__d, __s);                                                       \
        CPA16(__d + 16, __s + 4);                                              \
        asm volatile("cp.async.commit_group;" ::: "memory");                   \
    } while (0)

    // store 4 k's of A duplicated: Adup[k][arow] = {v,v} (8B per row)
#define STORE_A(st, v) do {                                                    \
        const uint32_t __ab = sb + (st) * ST_BYTES + OFF_A + arow * 8;         \
        asm volatile("st.shared.v2.f32 [%0], {%1,%1};"                         \
                     :: "r"(__ab + (apart*4+0)*1024), "f"((v).x) : "memory");  \
        asm volatile("st.shared.v2.f32 [%0], {%1,%1};"                         \
                     :: "r"(__ab + (apart*4+1)*1024), "f"((v).y) : "memory");  \
        asm volatile("st.shared.v2.f32 [%0], {%1,%1};"                         \
                     :: "r"(__ab + (apart*4+2)*1024), "f"((v).z) : "memory");  \
        asm volatile("st.shared.v2.f32 [%0], {%1,%1};"                         \
                     :: "r"(__ab + (apart*4+3)*1024), "f"((v).w) : "memory");  \
    } while (0)

    // ---- prologue: stage 0 ----
    {
        LOAD_B_ASYNC(0, 0);
        float4 v = __ldg((const float4*)Agp);
        STORE_A(0, v);
        asm volatile("cp.async.wait_group 0;" ::: "memory");
        __syncthreads();
    }

    // ---- main loop over 448 chunks of K=16 ----
    for (int c = 0; c < NCH; c++) {
        const int s   = c & 1;
        const bool np = (c + 1 < NCH);
        float4 av;
        if (np) {
            LOAD_B_ASYNC(c + 1, s ^ 1);
            av = __ldg((const float4*)(Agp + (size_t)(c + 1) * BK));
        }

        // A pairs: rows ty*4..+3 at +0, rows ty*4+64..+3 at +512B
        const uint32_t abase = sb + s * ST_BYTES + OFF_A + ty * 32;
        // B: 8 consecutive floats at col 8*tx
        const uint32_t bbase = sb + s * ST_BYTES + OFF_B + tx * 32;

        #pragma unroll 8
        for (int k = 0; k < BK; k++) {
            unsigned long long a2[8], b2[4];
            LDSV2U64(a2[0], a2[1], abase + k * 1024);          // rows ty*4+0,1
            LDSV2U64(a2[2], a2[3], abase + k * 1024 + 16);     // rows +2,+3
            LDSV2U64(a2[4], a2[5], abase + k * 1024 + 512);    // rows +64..
            LDSV2U64(a2[6], a2[7], abase + k * 1024 + 528);
            LDSV2U64(b2[0], b2[1], bbase + k * 1024);          // cols 8tx..+3
            LDSV2U64(b2[2], b2[3], bbase + k * 1024 + 16);     // cols +4..+7
            #pragma unroll
            for (int i = 0; i < 8; i++)
                #pragma unroll
                for (int j = 0; j < 4; j++)
                    asm("fma.rn.f32x2 %0, %1, %2, %0;"
                        : "+l"(c2[i][j]) : "l"(a2[i]), "l"(b2[j]));
        }

        if (np) {
            STORE_A(s ^ 1, av);
            asm volatile("cp.async.wait_group 0;" ::: "memory");
        }
        __syncthreads();
    }

    // ---- epilogue: logits -> SMEM (128 x 256 f32 = 128KB) ----
    float* slog = (float*)smem;
    #pragma unroll
    for (int i = 0; i < 8; i++) {
        const int r = (i < 4) ? (ty * 4 + i) : (ty * 4 + 60 + i);  // +64+(i-4)
        unsigned long long* dst =
            (unsigned long long*)(slog + (size_t)r * NEXP + tx * 8);
        dst[0] = c2[i][0]; dst[1] = c2[i][1];
        dst[2] = c2[i][2]; dst[3] = c2[i][3];
    }
    __syncthreads();

    // ---- fused routing: warp ty routes tokens ty*8 .. ty*8+7 ----
    #pragma unroll 1
    for (int t = 0; t < 8; t++) {
        const int lt = ty * 8 + t;
        route_one(slog + (size_t)lt * NEXP, bias, out, write_idx, bm + lt,
                  tx, 1);
    }
}

// ---------------------------------------------------------------------------
// Kernel 2: fp32 recompute + re-route for flagged tokens (validated R4-R9).
// ---------------------------------------------------------------------------
__global__ __launch_bounds__(256)
void recompute_kernel(const float* __restrict__ A, const float* __restrict__ W,
                      const float* __restrict__ bias, float* __restrict__ out,
                      int write_idx)
{
    __shared__ __align__(16) float srow[HIDDEN];
    __shared__ __align__(16) float slog[NEXP];

    const int nf   = g_nflag;
    const int wid  = threadIdx.x >> 5;
    const int lane = threadIdx.x & 31;

    for (int it = blockIdx.x; it < nf; it += gridDim.x) {
        const int token = g_flagged[it];
        for (int i = threadIdx.x * 4; i < HIDDEN; i += 1024)
            *(float4*)(srow + i) = *(const float4*)(A + (size_t)token * HIDDEN + i);
        __syncthreads();

        for (int e = wid * 32; e < wid * 32 + 32; e++) {
            const float* wr = W + (size_t)e * HIDDEN;
            float a0 = 0.f, a1 = 0.f;
            for (int i = lane * 4; i < HIDDEN; i += 256) {
                float4 wv = *(const float4*)(wr + i);
                float4 av = *(const float4*)(srow + i);
                a0 += av.x * wv.x + av.y * wv.y + av.z * wv.z + av.w * wv.w;
                float4 wv2 = *(const float4*)(wr + i + 128);
                float4 av2 = *(const float4*)(srow + i + 128);
                a1 += av2.x * wv2.x + av2.y * wv2.y + av2.z * wv2.z + av2.w * wv2.w;
            }
            float acc = a0 + a1;
            #pragma unroll
            for (int d = 16; d; d >>= 1)
                acc += __shfl_xor_sync(0xffffffffu, acc, d);
            if (lane == 0) slog[e] = acc;
        }
        __syncthreads();

        if (wid == 0)
            route_one(slog, bias, out, write_idx, token, lane, 0);
        __syncthreads();
    }
}

// ---------------------------------------------------------------------------
extern "C" void kernel_launch(void* const* d_in, const int* in_sizes, int n_in,
                              void* d_out, int out_size)
{
    const float* hs   = (const float*)d_in[0];  // [16384, 7168]
    const float* w    = (const float*)d_in[1];  // [256, 7168]
    const float* bias = (const float*)d_in[2];  // [256]
    float* out = (float*)d_out;

    cudaFuncSetAttribute(gemm_fx2,
                         cudaFuncAttributeMaxDynamicSharedMemorySize,
                         SMEM_TOTAL);

    const int write_idx = (out_size >= TOKENS * TOPK * 2) ? 1 : 0;

    convert_b_kernel<<<NCH, 256>>>(w);
    gemm_fx2<<<TOKENS / 128, 512, SMEM_TOTAL>>>(hs, bias, out, write_idx);
    recompute_kernel<<<128, 256>>>(hs, w, bias, out, write_idx);
}

// round 11
// speedup vs baseline: 1.1185x; 1.1185x over previous
#include <cuda_runtime.h>
#include <math_constants.h>
#include <math.h>
#include <cstdint>

#define TOKENS 16384
#define HIDDEN 7168
#define NEXP   256
#define TOPK   8
#define BM     64
#define BK     8
#define NK     (HIDDEN / BK)   // 896
#define TAU    1e-4f

// SMEM map (per CTA): [0, 64KB) logits 64x256 f32; then 2 load stages.
// Stage: A 8 planes x 68 floats (272B) = 2176B at OFF_A; B 8 planes x 264
// floats (1056B) = 8448B at OFF_B. Stage stride 10752B.
#define SLOG_BYTES 65536
#define ST_BYTES   10752
#define OFF_A      0
#define OFF_B      2304
#define A_PLANE    272
#define B_PLANE    1056
#define SMEM_TOTAL (SLOG_BYTES + 2 * ST_BYTES)   // 87040

__device__ int g_nflag;
__device__ int g_flagged[TOKENS];

#define LDS128F(v, addr) \
    asm volatile("ld.shared.v4.f32 {%0,%1,%2,%3}, [%4];" \
                 : "=f"((v).x), "=f"((v).y), "=f"((v).z), "=f"((v).w) : "r"(addr))

__global__ void init_flags_kernel() { g_nflag = 0; }

// ---------------------------------------------------------------------------
// route_one: reference-exact routing for one token (validated R4-R10).
// ---------------------------------------------------------------------------
__device__ __forceinline__ void route_one(const float* __restrict__ row,
                                          const float* __restrict__ bias,
                                          float* __restrict__ out,
                                          int write_idx, int token, int lane,
                                          int do_flag)
{
    const unsigned FULL = 0xffffffffu;

    float4 l0 = *(const float4*)(row + lane * 8);
    float4 l1 = *(const float4*)(row + lane * 8 + 4);
    float4 b0 = *(const float4*)(bias + lane * 8);
    float4 b1 = *(const float4*)(bias + lane * 8 + 4);

    float lv[8] = {l0.x, l0.y, l0.z, l0.w, l1.x, l1.y, l1.z, l1.w};
    float bb[8] = {b0.x, b0.y, b0.z, b0.w, b1.x, b1.y, b1.z, b1.w};
    float sc[8], s4[8];
    #pragma unroll
    for (int i = 0; i < 8; i++) {
        float s = 1.0f / (1.0f + expf(-lv[i]));
        sc[i] = s;
        s4[i] = s + bb[i];
    }

    float m1 = -CUDART_INF_F, m2 = -CUDART_INF_F, m3 = -CUDART_INF_F;
    #pragma unroll
    for (int i = 0; i < 8; i++) {
        float v = s4[i];
        if (v > m1)      { m3 = m2; m2 = m1; m1 = v; }
        else if (v > m2) { m3 = m2; m2 = v; }
        else if (v > m3) { m3 = v; }
    }
    #pragma unroll
    for (int d = 1; d <= 2; d <<= 1) {
        float o1 = __shfl_xor_sync(FULL, m1, d);
        float o2 = __shfl_xor_sync(FULL, m2, d);
        float o3 = __shfl_xor_sync(FULL, m3, d);
        float mn1 = fminf(m1, o1);
        float mx2 = fmaxf(m2, o2);
        float n1 = fmaxf(m1, o1);
        float n2 = fmaxf(mn1, mx2);
        float n3 = fmaxf(fminf(mn1, mx2), fmaxf(m3, o3));
        m1 = n1; m2 = n2; m3 = n3;
    }
    const float gs  = m1 + m2;
    const float m23 = m2 - m3;
    const int   g   = lane >> 2;

    int rank = 0;
    #pragma unroll
    for (int j = 0; j < 8; j++) {
        float gj = __shfl_sync(FULL, gs, j * 4);
        rank += (gj > gs) || (gj == gs && j < g);
    }
    const int selg = (rank < 4);
    if (!selg) {
        #pragma unroll
        for (int i = 0; i < 8; i++) s4[i] = 0.0f;   // reference: score * mask
    }

    float flagmin = CUDART_INF_F;
    if (do_flag) {
        float vsel = selg ? gs : CUDART_INF_F;
        float vuns = selg ? -CUDART_INF_F : gs;
        float mm   = m23;
        #pragma unroll
        for (int d = 16; d; d >>= 1) {
            vsel = fminf(vsel, __shfl_xor_sync(FULL, vsel, d));
            vuns = fmaxf(vuns, __shfl_xor_sync(FULL, vuns, d));
            mm   = fminf(mm,   __shfl_xor_sync(FULL, mm,   d));
        }
        flagmin = fminf(vsel - vuns, mm);
    }

    float wsum = 0.0f, my_w = 0.0f, prevv = 0.0f;
    int   my_ix = 0;
    #pragma unroll
    for (int t = 0; t < 8; t++) {
        float bv = s4[0]; int bp = 0;
        #pragma unroll
        for (int i = 1; i < 8; i++)
            if (s4[i] > bv) { bv = s4[i]; bp = i; }
        float v  = bv;
        int   ix = lane * 8 + bp;
        #pragma unroll
        for (int d = 16; d; d >>= 1) {
            float ov = __shfl_xor_sync(FULL, v, d);
            int   oi = __shfl_xor_sync(FULL, ix, d);
            if (ov > v || (ov == v && oi < ix)) { v = ov; ix = oi; }
        }
        if (t > 0) flagmin = fminf(flagmin, prevv - v);
        prevv = v;
        const int opos  = ix & 7;
        const int olane = ix >> 3;
        #pragma unroll
        for (int i = 0; i < 8; i++)
            if (lane == olane && i == opos) s4[i] = -CUDART_INF_F;
        float cand = sc[0];
        #pragma unroll
        for (int i = 1; i < 8; i++)
            if (i == opos) cand = sc[i];
        float w = __shfl_sync(FULL, cand, olane);
        wsum += w;
        if (lane == t) { my_w = w; my_ix = ix; }
    }

    if (do_flag) {
        float bv = s4[0];
        #pragma unroll
        for (int i = 1; i < 8; i++) bv = fmaxf(bv, s4[i]);
        #pragma unroll
        for (int d = 16; d; d >>= 1)
            bv = fmaxf(bv, __shfl_xor_sync(FULL, bv, d));
        flagmin = fminf(flagmin, prevv - bv);
        if (lane == 0 && flagmin < TAU) {
            int p = atomicAdd(&g_nflag, 1);
            g_flagged[p] = token;
        }
    }

    const float scale = 2.5f / (wsum + 1e-20f);
    if (lane < TOPK) {
        out[(size_t)token * TOPK + lane] = my_w * scale;
        if (write_idx)
            out[(size_t)TOKENS * TOPK + (size_t)token * TOPK + lane] = (float)my_ix;
    }
}

// ---------------------------------------------------------------------------
// Kernel 1: fused fp32 SGEMM + routing.
// R1's exact machinery extended to full-N: CTA = 64 tokens x 256 experts,
// 256 threads (occ 2 -> 16 warps/SM like R1), 8x8 per-thread tile, BK=8,
// LDG->reg->STS double buffer (NO cp.async), one sync per chunk.
// A-fragment loads are warp-broadcast; all STS/LDS conflict-free via
// padded plane strides (A: 68 floats, B: 264 floats).
// Epilogue: logits -> SMEM, route in-CTA.
// ---------------------------------------------------------------------------
__global__ __launch_bounds__(256, 2)
void gemm_fused(const float* __restrict__ A, const float* __restrict__ W,
                const float* __restrict__ bias, float* __restrict__ out,
                int write_idx)
{
    extern __shared__ char smem[];
    uint32_t sb;
    asm("{ .reg .u64 t; cvta.to.shared.u64 t, %1; cvt.u32.u64 %0, t; }"
        : "=r"(sb) : "l"((void*)smem));
    const uint32_t stg = sb + SLOG_BYTES;

    const int tid = threadIdx.x;
    const int ng  = tid & 31;           // N: cols ng*4 and ng*4+128
    const int mg  = tid >> 5;           // M: rows mg*4..+3 and mg*4+32..+3
    const int bm  = blockIdx.x * BM;

    // A loader: 4 threads/row, 2 consecutive k each
    const int arow  = tid >> 2;         // 0..63
    const int apart = tid & 3;          // k pair 2*apart, 2*apart+1
    const float* Agp = A + (size_t)(bm + arow) * HIDDEN + apart * 2;
    // B loader: thread t loads expert row t, all 8 k
    const float* Bgp = W + (size_t)tid * HIDDEN;

    float cc[8][8];
    #pragma unroll
    for (int i = 0; i < 8; i++)
        #pragma unroll
        for (int j = 0; j < 8; j++) cc[i][j] = 0.0f;

#define LOAD_GL(nc, a2, b40, b41) do {                                         \
        a2  = __ldg((const float2*)(Agp + (size_t)(nc) * BK));                 \
        b40 = __ldg((const float4*)(Bgp + (size_t)(nc) * BK));                 \
        b41 = __ldg((const float4*)(Bgp + (size_t)(nc) * BK + 4));             \
    } while (0)

#define STORE_ST(st, a2, b40, b41) do {                                        \
        const uint32_t __sa = stg + (st) * ST_BYTES + OFF_A + arow * 4;        \
        asm volatile("st.shared.f32 [%0], %1;"                                 \
            :: "r"(__sa + (2*apart)   * A_PLANE), "f"((a2).x) : "memory");     \
        asm volatile("st.shared.f32 [%0], %1;"                                 \
            :: "r"(__sa + (2*apart+1) * A_PLANE), "f"((a2).y) : "memory");     \
        const uint32_t __sbp = stg + (st) * ST_BYTES + OFF_B + tid * 4;        \
        asm volatile("st.shared.f32 [%0], %1;" :: "r"(__sbp + 0*B_PLANE), "f"((b40).x) : "memory"); \
        asm volatile("st.shared.f32 [%0], %1;" :: "r"(__sbp + 1*B_PLANE), "f"((b40).y) : "memory"); \
        asm volatile("st.shared.f32 [%0], %1;" :: "r"(__sbp + 2*B_PLANE), "f"((b40).z) : "memory"); \
        asm volatile("st.shared.f32 [%0], %1;" :: "r"(__sbp + 3*B_PLANE), "f"((b40).w) : "memory"); \
        asm volatile("st.shared.f32 [%0], %1;" :: "r"(__sbp + 4*B_PLANE), "f"((b41).x) : "memory"); \
        asm volatile("st.shared.f32 [%0], %1;" :: "r"(__sbp + 5*B_PLANE), "f"((b41).y) : "memory"); \
        asm volatile("st.shared.f32 [%0], %1;" :: "r"(__sbp + 6*B_PLANE), "f"((b41).z) : "memory"); \
        asm volatile("st.shared.f32 [%0], %1;" :: "r"(__sbp + 7*B_PLANE), "f"((b41).w) : "memory"); \
    } while (0)

    // ---- prologue: stage 0 ----
    {
        float2 a2; float4 b40, b41;
        LOAD_GL(0, a2, b40, b41);
        STORE_ST(0, a2, b40, b41);
        __syncthreads();
    }

    // ---- main loop over 896 chunks of K=8 ----
    for (int c = 0; c < NK; c++) {
        const int s   = c & 1;
        const bool np = (c + 1 < NK);
        float2 a2; float4 b40, b41;
        if (np) LOAD_GL(c + 1, a2, b40, b41);

        const uint32_t abase = stg + s * ST_BYTES + OFF_A + mg * 16;
        const uint32_t bbase = stg + s * ST_BYTES + OFF_B + ng * 16;

        #pragma unroll
        for (int k = 0; k < BK; k++) {
            float4 va0, va1, vb0, vb1;
            LDS128F(va0, abase + k * A_PLANE);          // rows mg*4..+3 (bcast)
            LDS128F(va1, abase + k * A_PLANE + 128);    // rows mg*4+32..
            LDS128F(vb0, bbase + k * B_PLANE);          // cols ng*4..+3
            LDS128F(vb1, bbase + k * B_PLANE + 512);    // cols ng*4+128..
            float ar[8] = {va0.x, va0.y, va0.z, va0.w, va1.x, va1.y, va1.z, va1.w};
            float br[8] = {vb0.x, vb0.y, vb0.z, vb0.w, vb1.x, vb1.y, vb1.z, vb1.w};
            #pragma unroll
            for (int i = 0; i < 8; i++)
                #pragma unroll
                for (int j = 0; j < 8; j++)
                    cc[i][j] += ar[i] * br[j];
        }

        if (np) STORE_ST(s ^ 1, a2, b40, b41);
        __syncthreads();
    }

    // ---- epilogue: logits -> SMEM (64 x 256 f32 = 64KB) ----
    float* slog = (float*)smem;
    #pragma unroll
    for (int i = 0; i < 8; i++) {
        const int r = mg * 4 + ((i < 4) ? i : (28 + i));   // +32+(i-4)
        float* dst = slog + (size_t)r * NEXP + ng * 4;
        dst[0] = cc[i][0]; dst[1] = cc[i][1];
        dst[2] = cc[i][2]; dst[3] = cc[i][3];
        dst[128] = cc[i][4]; dst[129] = cc[i][5];
        dst[130] = cc[i][6]; dst[131] = cc[i][7];
    }
    __syncthreads();

    // ---- fused routing: warp mg routes tokens mg*8 .. mg*8+7 ----
    #pragma unroll 1
    for (int t = 0; t < 8; t++) {
        const int lt = mg * 8 + t;
        route_one(slog + (size_t)lt * NEXP, bias, out, write_idx, bm + lt,
                  ng, 1);
    }
}

// ---------------------------------------------------------------------------
// Kernel 2: fp32 recompute + re-route for flagged tokens (validated R4-R10).
// ---------------------------------------------------------------------------
__global__ __launch_bounds__(256)
void recompute_kernel(const float* __restrict__ A, const float* __restrict__ W,
                      const float* __restrict__ bias, float* __restrict__ out,
                      int write_idx)
{
    __shared__ __align__(16) float srow[HIDDEN];
    __shared__ __align__(16) float slog[NEXP];

    const int nf   = g_nflag;
    const int wid  = threadIdx.x >> 5;
    const int lane = threadIdx.x & 31;

    for (int it = blockIdx.x; it < nf; it += gridDim.x) {
        const int token = g_flagged[it];
        for (int i = threadIdx.x * 4; i < HIDDEN; i += 1024)
            *(float4*)(srow + i) = *(const float4*)(A + (size_t)token * HIDDEN + i);
        __syncthreads();

        for (int e = wid * 32; e < wid * 32 + 32; e++) {
            const float* wr = W + (size_t)e * HIDDEN;
            float a0 = 0.f, a1 = 0.f;
            for (int i = lane * 4; i < HIDDEN; i += 256) {
                float4 wv = *(const float4*)(wr + i);
                float4 av = *(const float4*)(srow + i);
                a0 += av.x * wv.x + av.y * wv.y + av.z * wv.z + av.w * wv.w;
                float4 wv2 = *(const float4*)(wr + i + 128);
                float4 av2 = *(const float4*)(srow + i + 128);
                a1 += av2.x * wv2.x + av2.y * wv2.y + av2.z * wv2.z + av2.w * wv2.w;
            }
            float acc = a0 + a1;
            #pragma unroll
            for (int d = 16; d; d >>= 1)
                acc += __shfl_xor_sync(0xffffffffu, acc, d);
            if (lane == 0) slog[e] = acc;
        }
        __syncthreads();

        if (wid == 0)
            route_one(slog, bias, out, write_idx, token, lane, 0);
        __syncthreads();
    }
}

// ---------------------------------------------------------------------------
extern "C" void kernel_launch(void* const* d_in, const int* in_sizes, int n_in,
                              void* d_out, int out_size)
{
    const float* hs   = (const float*)d_in[0];  // [16384, 7168]
    const float* w    = (const float*)d_in[1];  // [256, 7168]
    const float* bias = (const float*)d_in[2];  // [256]
    float* out = (float*)d_out;

    cudaFuncSetAttribute(gemm_fused,
                         cudaFuncAttributeMaxDynamicSharedMemorySize,
                         SMEM_TOTAL);

    const int write_idx = (out_size >= TOKENS * TOPK * 2) ? 1 : 0;

    init_flags_kernel<<<1, 1>>>();
    gemm_fused<<<TOKENS / BM, 256, SMEM_TOTAL>>>(hs, w, bias, out, write_idx);
    recompute_kernel<<<128, 256>>>(hs, w, bias, out, write_idx);
}